// round 1
// baseline (speedup 1.0000x reference)
#include <cuda_runtime.h>
#include <cuda_bf16.h>
#include <math.h>

// ---------------- problem constants ----------------
#define BB   4
#define TT   4096
#define DD   1024
#define HH   16
#define HD   64
#define DFF_ 4096
#define KSEL 2048              // ceil(0.5 * T)
#define MR   (BB * KSEL)       // 8192 selected rows total
#define EPS_LN 1e-5f

// ---------------- device scratch (static: no allocation allowed) ----------------
__device__ float  g_logit[BB * TT];
__device__ double g_bsum[BB];
__device__ int    g_idx[MR];
__device__ float  g_xsel[(size_t)MR * DD];        // 32 MB  residual stream
__device__ float  g_normed[(size_t)MR * DD];      // 32 MB
__device__ float  g_qkv[(size_t)MR * 3 * DD];     // 96 MB
__device__ float  g_o[(size_t)MR * DD];           // 32 MB
__device__ float  g_h1[(size_t)MR * DFF_];        // 128 MB
__device__ float  g_h2[(size_t)MR * DFF_];        // 128 MB

// ---------------- init ----------------
__global__ void init_kernel() {
    if (threadIdx.x < BB) g_bsum[threadIdx.x] = 0.0;
}

// ---------------- router: logits (double accum) + sigmoid batch sums ----------------
__global__ void __launch_bounds__(256) router_kernel(const float* __restrict__ x,
                                                     const float* __restrict__ w) {
    int warp = threadIdx.x >> 5, lane = threadIdx.x & 31;
    int row  = blockIdx.x * 8 + warp;          // < B*T
    const float* xr = x + (size_t)row * DD;
    double acc = 0.0;
    #pragma unroll 8
    for (int i = lane; i < DD; i += 32) acc += (double)xr[i] * (double)w[i];
    #pragma unroll
    for (int o = 16; o > 0; o >>= 1) acc += __shfl_down_sync(0xffffffffu, acc, o);
    if (lane == 0) {
        g_logit[row] = (float)acc;
        double sig = 1.0 / (1.0 + exp(-acc));
        atomicAdd(&g_bsum[row / TT], sig);
    }
}

// ---------------- aux loss (unbiased variance of per-batch mean scores) ----------------
__global__ void aux_kernel(float* out, size_t aux_idx) {
    if (threadIdx.x == 0) {
        double m[BB], mu = 0.0;
        for (int b = 0; b < BB; b++) { m[b] = g_bsum[b] / (double)TT; mu += m[b]; }
        mu /= (double)BB;
        double v = 0.0;
        for (int b = 0; b < BB; b++) { double d = m[b] - mu; v += d * d; }
        v /= (double)(BB - 1);
        out[aux_idx] = (float)v;
    }
}

// ---------------- per-batch top-k via bitonic sort ----------------
__global__ void __launch_bounds__(1024) topk_kernel() {
    __shared__ unsigned long long keys[TT];     // 32 KB
    int b = blockIdx.x, tid = threadIdx.x;
    for (int i = tid; i < TT; i += 1024) {
        unsigned u = __float_as_uint(g_logit[b * TT + i]);
        u = (u & 0x80000000u) ? ~u : (u | 0x80000000u);   // orderable ascending
        u = ~u;                                           // descending score
        keys[i] = ((unsigned long long)u << 32) | (unsigned)i;  // tie: lowest index first
    }
    __syncthreads();
    for (int k = 2; k <= TT; k <<= 1)
        for (int j = k >> 1; j > 0; j >>= 1) {
            for (int i = tid; i < TT; i += 1024) {
                int ixj = i ^ j;
                if (ixj > i) {
                    bool up = ((i & k) == 0);
                    unsigned long long a = keys[i], c = keys[ixj];
                    if ((a > c) == up) { keys[i] = c; keys[ixj] = a; }
                }
            }
            __syncthreads();
        }
    // first KSEL entries are the selected tokens; sort their indices ascending
    int* sidx = (int*)&keys[KSEL];              // upper half reused, no overlap
    for (int i = tid; i < KSEL; i += 1024)
        sidx[i] = (int)(unsigned)(keys[i] & 0xFFFFFFFFull);
    __syncthreads();
    for (int k = 2; k <= KSEL; k <<= 1)
        for (int j = k >> 1; j > 0; j >>= 1) {
            for (int i = tid; i < KSEL; i += 1024) {
                int ixj = i ^ j;
                if (ixj > i) {
                    bool up = ((i & k) == 0);
                    int a = sidx[i], c = sidx[ixj];
                    if ((a > c) == up) { sidx[i] = c; sidx[ixj] = a; }
                }
            }
            __syncthreads();
        }
    for (int i = tid; i < KSEL; i += 1024) g_idx[b * KSEL + i] = sidx[i];
}

// ---------------- gather + LayerNorm1 ----------------
__global__ void __launch_bounds__(256) gather_ln1_kernel(const float* __restrict__ x,
                                                         const float* __restrict__ sc,
                                                         const float* __restrict__ bi) {
    __shared__ float red[18];
    int r = blockIdx.x;
    int b = r >> 11;                             // r / KSEL
    int tok = g_idx[r];
    const float* src = x + ((size_t)b * TT + tok) * DD;
    int t = threadIdx.x;
    float v[4], s = 0.f, q = 0.f;
    #pragma unroll
    for (int j = 0; j < 4; j++) { v[j] = src[t + 256 * j]; s += v[j]; q += v[j] * v[j]; }
    #pragma unroll
    for (int o = 16; o > 0; o >>= 1) { s += __shfl_xor_sync(~0u, s, o); q += __shfl_xor_sync(~0u, q, o); }
    int w = t >> 5, lane = t & 31;
    if (lane == 0) { red[w] = s; red[w + 8] = q; }
    __syncthreads();
    if (t == 0) {
        float ss = 0, qq = 0;
        #pragma unroll
        for (int i = 0; i < 8; i++) { ss += red[i]; qq += red[i + 8]; }
        red[16] = ss; red[17] = qq;
    }
    __syncthreads();
    float mean = red[16] * (1.f / DD);
    float var  = red[17] * (1.f / DD) - mean * mean;
    float inv  = rsqrtf(var + EPS_LN);
    float* xs = g_xsel   + (size_t)r * DD;
    float* nm = g_normed + (size_t)r * DD;
    #pragma unroll
    for (int j = 0; j < 4; j++) {
        int c = t + 256 * j;
        xs[c] = v[j];
        nm[c] = (v[j] - mean) * inv * sc[c] + bi[c];
    }
}

// ---------------- LayerNorm2 (reads g_xsel) ----------------
__global__ void __launch_bounds__(256) ln2_kernel(const float* __restrict__ sc,
                                                  const float* __restrict__ bi) {
    __shared__ float red[18];
    int r = blockIdx.x;
    const float* src = g_xsel + (size_t)r * DD;
    int t = threadIdx.x;
    float v[4], s = 0.f, q = 0.f;
    #pragma unroll
    for (int j = 0; j < 4; j++) { v[j] = src[t + 256 * j]; s += v[j]; q += v[j] * v[j]; }
    #pragma unroll
    for (int o = 16; o > 0; o >>= 1) { s += __shfl_xor_sync(~0u, s, o); q += __shfl_xor_sync(~0u, q, o); }
    int w = t >> 5, lane = t & 31;
    if (lane == 0) { red[w] = s; red[w + 8] = q; }
    __syncthreads();
    if (t == 0) {
        float ss = 0, qq = 0;
        #pragma unroll
        for (int i = 0; i < 8; i++) { ss += red[i]; qq += red[i + 8]; }
        red[16] = ss; red[17] = qq;
    }
    __syncthreads();
    float mean = red[16] * (1.f / DD);
    float var  = red[17] * (1.f / DD) - mean * mean;
    float inv  = rsqrtf(var + EPS_LN);
    float* nm = g_normed + (size_t)r * DD;
    #pragma unroll
    for (int j = 0; j < 4; j++) {
        int c = t + 256 * j;
        nm[c] = (v[j] - mean) * inv * sc[c] + bi[c];
    }
}

// ---------------- SGEMM: C[M,N] (+)= A[M,K] * B[N,K]^T ----------------
// 128x128 block tile, BK=8, 256 threads, 8x8 per-thread, register prefetch.
// All M,N divisible by 128 and K by 8 in this problem -> no bounds checks.
template<int ADD>
__global__ void __launch_bounds__(256) sgemm_nt(const float* __restrict__ A,
                                                const float* __restrict__ B,
                                                float* __restrict__ C,
                                                int M, int N, int K) {
    __shared__ float As[8][128];
    __shared__ float Bs[8][128];
    const int tid = threadIdx.x;
    const int bm = blockIdx.y * 128, bn = blockIdx.x * 128;
    const int lr = tid >> 1;
    const int lc = (tid & 1) << 2;
    const float* Ap = A + (size_t)(bm + lr) * K + lc;
    const float* Bp = B + (size_t)(bn + lr) * K + lc;
    const int ty = tid >> 4, tx = tid & 15;
    float acc[8][8];
    #pragma unroll
    for (int i = 0; i < 8; i++)
        #pragma unroll
        for (int j = 0; j < 8; j++) acc[i][j] = 0.f;
    float4 a = *(const float4*)Ap;
    float4 b = *(const float4*)Bp;
    for (int k0 = 0; k0 < K; k0 += 8) {
        As[lc + 0][lr] = a.x; As[lc + 1][lr] = a.y; As[lc + 2][lr] = a.z; As[lc + 3][lr] = a.w;
        Bs[lc + 0][lr] = b.x; Bs[lc + 1][lr] = b.y; Bs[lc + 2][lr] = b.z; Bs[lc + 3][lr] = b.w;
        __syncthreads();
        if (k0 + 8 < K) { a = *(const float4*)(Ap + k0 + 8); b = *(const float4*)(Bp + k0 + 8); }
        #pragma unroll
        for (int kk = 0; kk < 8; kk++) {
            float ar[8], br[8];
            *(float4*)(ar)     = *(const float4*)(&As[kk][ty * 8]);
            *(float4*)(ar + 4) = *(const float4*)(&As[kk][ty * 8 + 4]);
            *(float4*)(br)     = *(const float4*)(&Bs[kk][tx * 8]);
            *(float4*)(br + 4) = *(const float4*)(&Bs[kk][tx * 8 + 4]);
            #pragma unroll
            for (int i = 0; i < 8; i++)
                #pragma unroll
                for (int j = 0; j < 8; j++)
                    acc[i][j] += ar[i] * br[j];
        }
        __syncthreads();
    }
    #pragma unroll
    for (int i = 0; i < 8; i++) {
        float* Cp = C + (size_t)(bm + ty * 8 + i) * N + bn + tx * 8;
        if (ADD) {
            float4 c0 = *(float4*)Cp, c1 = *(float4*)(Cp + 4);
            c0.x += acc[i][0]; c0.y += acc[i][1]; c0.z += acc[i][2]; c0.w += acc[i][3];
            c1.x += acc[i][4]; c1.y += acc[i][5]; c1.z += acc[i][6]; c1.w += acc[i][7];
            *(float4*)Cp = c0; *(float4*)(Cp + 4) = c1;
        } else {
            float4 c0 = make_float4(acc[i][0], acc[i][1], acc[i][2], acc[i][3]);
            float4 c1 = make_float4(acc[i][4], acc[i][5], acc[i][6], acc[i][7]);
            *(float4*)Cp = c0; *(float4*)(Cp + 4) = c1;
        }
    }
}

// ---------------- flash attention (fp32, 64x64 tiles, online softmax) ----------------
// grid: (KSEL/64, H, B), 256 threads (16x16), each thread owns 4x4 of O tile.
__global__ void __launch_bounds__(256) flash_kernel() {
    __shared__ float Qt[64][64];   // [d][q]  (transposed)
    __shared__ float Kt[64][64];   // [d][kv] (transposed); reused as Pt[kv][q]
    __shared__ float Vs[64][64];   // [kv][d] (natural)
    const int b = blockIdx.z, h = blockIdx.y, qt = blockIdx.x;
    const int tid = threadIdx.x, ty = tid >> 4, tx = tid & 15;
    const float* base = g_qkv + (size_t)b * KSEL * (3 * DD);
    // load Q tile transposed (once)
    {
        int r = tid >> 2, c0 = (tid & 3) * 4;
        const float* Qg = base + (size_t)(qt * 64) * (3 * DD) + h * HD;
        #pragma unroll
        for (int it = 0; it < 4; it++) {
            int c = it * 16 + c0;
            float4 v = *(const float4*)(Qg + (size_t)r * (3 * DD) + c);
            Qt[c][r] = v.x; Qt[c + 1][r] = v.y; Qt[c + 2][r] = v.z; Qt[c + 3][r] = v.w;
        }
    }
    float o[4][4], m_[4], l_[4];
    #pragma unroll
    for (int i = 0; i < 4; i++) {
        m_[i] = -1e30f; l_[i] = 0.f;
        #pragma unroll
        for (int j = 0; j < 4; j++) o[i][j] = 0.f;
    }
    for (int kt = 0; kt < KSEL / 64; kt++) {
        __syncthreads();  // previous tile's P/V reads done (also covers Q load at kt=0)
        {
            int r = tid >> 2, c0 = (tid & 3) * 4;
            const float* Kg = base + (size_t)(kt * 64) * (3 * DD) + DD + h * HD;
            const float* Vg = base + (size_t)(kt * 64) * (3 * DD) + 2 * DD + h * HD;
            #pragma unroll
            for (int it = 0; it < 4; it++) {
                int c = it * 16 + c0;
                float4 kv4 = *(const float4*)(Kg + (size_t)r * (3 * DD) + c);
                Kt[c][r] = kv4.x; Kt[c + 1][r] = kv4.y; Kt[c + 2][r] = kv4.z; Kt[c + 3][r] = kv4.w;
                float4 vv = *(const float4*)(Vg + (size_t)r * (3 * DD) + c);
                *(float4*)&Vs[r][c] = vv;
            }
        }
        __syncthreads();
        // S = Q K^T (scaled)
        float s[4][4];
        #pragma unroll
        for (int i = 0; i < 4; i++)
            #pragma unroll
            for (int j = 0; j < 4; j++) s[i][j] = 0.f;
        #pragma unroll 8
        for (int d = 0; d < 64; d++) {
            float aq[4], bk[4];
            #pragma unroll
            for (int i = 0; i < 4; i++) aq[i] = Qt[d][ty * 4 + i];
            #pragma unroll
            for (int j = 0; j < 4; j++) bk[j] = Kt[d][tx * 4 + j];
            #pragma unroll
            for (int i = 0; i < 4; i++)
                #pragma unroll
                for (int j = 0; j < 4; j++)
                    s[i][j] += aq[i] * bk[j];
        }
        // online softmax (row reductions across 16-lane groups)
        #pragma unroll
        for (int i = 0; i < 4; i++) {
            float tm = -1e30f;
            #pragma unroll
            for (int j = 0; j < 4; j++) { s[i][j] *= 0.125f; tm = fmaxf(tm, s[i][j]); }
            #pragma unroll
            for (int off = 1; off < 16; off <<= 1) tm = fmaxf(tm, __shfl_xor_sync(~0u, tm, off));
            float nm = fmaxf(m_[i], tm);
            float corr = __expf(m_[i] - nm);
            float rs = 0.f;
            #pragma unroll
            for (int j = 0; j < 4; j++) { s[i][j] = __expf(s[i][j] - nm); rs += s[i][j]; }
            #pragma unroll
            for (int off = 1; off < 16; off <<= 1) rs += __shfl_xor_sync(~0u, rs, off);
            l_[i] = l_[i] * corr + rs;
            #pragma unroll
            for (int j = 0; j < 4; j++) o[i][j] *= corr;
            m_[i] = nm;
        }
        __syncthreads();   // all Kt reads done before overwrite with P
        #pragma unroll
        for (int i = 0; i < 4; i++)
            #pragma unroll
            for (int j = 0; j < 4; j++)
                Kt[tx * 4 + j][ty * 4 + i] = s[i][j];   // Pt[kv][q]
        __syncthreads();
        // O += P V
        #pragma unroll 8
        for (int kv = 0; kv < 64; kv++) {
            float p[4], vv[4];
            #pragma unroll
            for (int i = 0; i < 4; i++) p[i] = Kt[kv][ty * 4 + i];
            #pragma unroll
            for (int j = 0; j < 4; j++) vv[j] = Vs[kv][tx * 4 + j];
            #pragma unroll
            for (int i = 0; i < 4; i++)
                #pragma unroll
                for (int j = 0; j < 4; j++)
                    o[i][j] += p[i] * vv[j];
        }
    }
    #pragma unroll
    for (int i = 0; i < 4; i++) {
        float inv = 1.f / l_[i];
        size_t row = (size_t)(b * KSEL + qt * 64 + ty * 4 + i);
        #pragma unroll
        for (int j = 0; j < 4; j++)
            g_o[row * DD + h * HD + tx * 4 + j] = o[i][j] * inv;
    }
}

// ---------------- SwiGLU elementwise: h1 = silu(h1) * h2 ----------------
__global__ void __launch_bounds__(256) swiglu_kernel() {
    size_t i = (size_t)blockIdx.x * blockDim.x + threadIdx.x;   // float4 index
    float4 a = ((const float4*)g_h1)[i];
    float4 c = ((const float4*)g_h2)[i];
    a.x = a.x / (1.f + __expf(-a.x)) * c.x;
    a.y = a.y / (1.f + __expf(-a.y)) * c.y;
    a.z = a.z / (1.f + __expf(-a.z)) * c.z;
    a.w = a.w / (1.f + __expf(-a.w)) * c.w;
    ((float4*)g_h1)[i] = a;
}

// ---------------- passthrough copy + scatter ----------------
__global__ void __launch_bounds__(256) copy_kernel(float* __restrict__ out,
                                                   const float* __restrict__ x) {
    size_t i = (size_t)blockIdx.x * blockDim.x + threadIdx.x;   // float4 index
    ((float4*)out)[i] = ((const float4*)x)[i];
}

__global__ void __launch_bounds__(256) scatter_kernel(float* __restrict__ out) {
    int r = blockIdx.x;
    int b = r >> 11;
    int tok = g_idx[r];
    float4 v = ((const float4*)(g_xsel + (size_t)r * DD))[threadIdx.x];
    ((float4*)(out + ((size_t)b * TT + tok) * DD))[threadIdx.x] = v;
}

// ---------------- launcher ----------------
extern "C" void kernel_launch(void* const* d_in, const int* in_sizes, int n_in,
                              void* d_out, int out_size) {
    const float* x        = (const float*)d_in[0];
    const float* w_router = (const float*)d_in[1];
    const float* ln1s     = (const float*)d_in[2];
    const float* ln1b     = (const float*)d_in[3];
    const float* ln2s     = (const float*)d_in[4];
    const float* ln2b     = (const float*)d_in[5];
    const float* w_qkv    = (const float*)d_in[6];
    const float* w_out    = (const float*)d_in[7];
    const float* w1       = (const float*)d_in[8];
    const float* w2       = (const float*)d_in[9];
    const float* w3       = (const float*)d_in[10];
    float* out = (float*)d_out;

    float *p_xsel, *p_normed, *p_qkv, *p_o, *p_h1, *p_h2;
    cudaGetSymbolAddress((void**)&p_xsel,   g_xsel);
    cudaGetSymbolAddress((void**)&p_normed, g_normed);
    cudaGetSymbolAddress((void**)&p_qkv,    g_qkv);
    cudaGetSymbolAddress((void**)&p_o,      g_o);
    cudaGetSymbolAddress((void**)&p_h1,     g_h1);
    cudaGetSymbolAddress((void**)&p_h2,     g_h2);

    init_kernel<<<1, 32>>>();
    router_kernel<<<(BB * TT) / 8, 256>>>(x, w_router);
    if (out_size > BB * TT * DD)
        aux_kernel<<<1, 32>>>(out, (size_t)out_size - 1);
    topk_kernel<<<BB, 1024>>>();
    gather_ln1_kernel<<<MR, 256>>>(x, ln1s, ln1b);

    // QKV: (8192 x 3072) = normed (8192 x 1024) @ w_qkv^T
    sgemm_nt<0><<<dim3(3 * DD / 128, MR / 128), 256>>>(p_normed, w_qkv, p_qkv, MR, 3 * DD, DD);
    // attention -> g_o
    flash_kernel<<<dim3(KSEL / 64, HH, BB), 256>>>();
    // x_sel += o @ w_out^T
    sgemm_nt<1><<<dim3(DD / 128, MR / 128), 256>>>(p_o, w_out, p_xsel, MR, DD, DD);
    // LN2
    ln2_kernel<<<MR, 256>>>(ln2s, ln2b);
    // FFN
    sgemm_nt<0><<<dim3(DFF_ / 128, MR / 128), 256>>>(p_normed, w1, p_h1, MR, DFF_, DD);
    sgemm_nt<0><<<dim3(DFF_ / 128, MR / 128), 256>>>(p_normed, w2, p_h2, MR, DFF_, DD);
    swiglu_kernel<<<((size_t)MR * DFF_ / 4) / 256, 256>>>();
    sgemm_nt<1><<<dim3(DD / 128, MR / 128), 256>>>(p_h1, w3, p_xsel, MR, DD, DFF_);

    // assemble output: passthrough copy then scatter processed rows
    copy_kernel<<<((size_t)BB * TT * DD / 4) / 256, 256>>>(out, x);
    scatter_kernel<<<MR, 256>>>(out);
}

// round 3
// speedup vs baseline: 3.3407x; 3.3407x over previous
#include <cuda_runtime.h>
#include <cuda_bf16.h>
#include <math.h>
#include <stdint.h>

// ---------------- problem constants ----------------
#define BB   4
#define TT   4096
#define DD   1024
#define HH   16
#define HD   64
#define DFF_ 4096
#define KSEL 2048
#define MR   (BB * KSEL)
#define EPS_LN 1e-5f

// ---------------- device scratch ----------------
__device__ float  g_logit[BB * TT];
__device__ double g_bsum[BB];
__device__ int    g_idx[MR];
__device__ float  g_xsel[(size_t)MR * DD];
__device__ float  g_normed[(size_t)MR * DD];
__device__ float  g_qkv[(size_t)MR * 3 * DD];
__device__ float  g_o[(size_t)MR * DD];
__device__ float  g_h1[(size_t)MR * DFF_];
__device__ float  g_h2[(size_t)MR * DFF_];
// tf32-rounded weight copies
__device__ float  g_wqkv_r[3 * DD * DD];
__device__ float  g_wout_r[DD * DD];
__device__ float  g_w1_r[(size_t)DFF_ * DD];
__device__ float  g_w2_r[(size_t)DFF_ * DD];
__device__ float  g_w3_r[(size_t)DD * DFF_];

// ---------------- helpers ----------------
__device__ __forceinline__ float to_tf32(float x) {
    uint32_t u;
    asm("cvt.rna.tf32.f32 %0, %1;" : "=r"(u) : "f"(x));
    return __uint_as_float(u);
}
__device__ __forceinline__ uint32_t smem_u32(const void* p) {
    uint32_t a;
    asm("{ .reg .u64 t; cvta.to.shared.u64 t, %1; cvt.u32.u64 %0, t; }" : "=r"(a) : "l"(p));
    return a;
}
__device__ __forceinline__ void cp16(uint32_t dst, const void* src) {
    asm volatile("cp.async.cg.shared.global [%0], [%1], 16;" :: "r"(dst), "l"(src));
}
__device__ __forceinline__ void cp_commit() { asm volatile("cp.async.commit_group;" ::: "memory"); }
__device__ __forceinline__ void cp_wait2()  { asm volatile("cp.async.wait_group 2;"  ::: "memory"); }

__device__ __forceinline__ void mma_tf32(float c[4],
                                         uint32_t a0, uint32_t a1, uint32_t a2, uint32_t a3,
                                         uint32_t b0, uint32_t b1) {
    asm volatile("mma.sync.aligned.m16n8k8.row.col.f32.tf32.tf32.f32 "
        "{%0,%1,%2,%3}, {%4,%5,%6,%7}, {%8,%9}, {%0,%1,%2,%3};"
        : "+f"(c[0]), "+f"(c[1]), "+f"(c[2]), "+f"(c[3])
        : "r"(a0), "r"(a1), "r"(a2), "r"(a3), "r"(b0), "r"(b1));
}

// ---------------- init ----------------
__global__ void init_kernel() {
    if (threadIdx.x < BB) g_bsum[threadIdx.x] = 0.0;
}

// ---------------- round weights to tf32 ----------------
__global__ void __launch_bounds__(256) round_tf32_kernel(float* __restrict__ dst,
                                                         const float* __restrict__ src) {
    size_t i = (size_t)blockIdx.x * 256 + threadIdx.x;
    float4 v = ((const float4*)src)[i];
    v.x = to_tf32(v.x); v.y = to_tf32(v.y); v.z = to_tf32(v.z); v.w = to_tf32(v.w);
    ((float4*)dst)[i] = v;
}

// ---------------- router ----------------
__global__ void __launch_bounds__(256) router_kernel(const float* __restrict__ x,
                                                     const float* __restrict__ w) {
    int warp = threadIdx.x >> 5, lane = threadIdx.x & 31;
    int row  = blockIdx.x * 8 + warp;
    const float* xr = x + (size_t)row * DD;
    double acc = 0.0;
    #pragma unroll 8
    for (int i = lane; i < DD; i += 32) acc += (double)xr[i] * (double)w[i];
    #pragma unroll
    for (int o = 16; o > 0; o >>= 1) acc += __shfl_down_sync(0xffffffffu, acc, o);
    if (lane == 0) {
        g_logit[row] = (float)acc;
        double sig = 1.0 / (1.0 + exp(-acc));
        atomicAdd(&g_bsum[row / TT], sig);
    }
}

__global__ void aux_kernel(float* out, size_t aux_idx) {
    if (threadIdx.x == 0) {
        double m[BB], mu = 0.0;
        for (int b = 0; b < BB; b++) { m[b] = g_bsum[b] / (double)TT; mu += m[b]; }
        mu /= (double)BB;
        double v = 0.0;
        for (int b = 0; b < BB; b++) { double d = m[b] - mu; v += d * d; }
        v /= (double)(BB - 1);
        out[aux_idx] = (float)v;
    }
}

// ---------------- top-k ----------------
__global__ void __launch_bounds__(1024) topk_kernel() {
    __shared__ unsigned long long keys[TT];
    int b = blockIdx.x, tid = threadIdx.x;
    for (int i = tid; i < TT; i += 1024) {
        unsigned u = __float_as_uint(g_logit[b * TT + i]);
        u = (u & 0x80000000u) ? ~u : (u | 0x80000000u);
        u = ~u;
        keys[i] = ((unsigned long long)u << 32) | (unsigned)i;
    }
    __syncthreads();
    for (int k = 2; k <= TT; k <<= 1)
        for (int j = k >> 1; j > 0; j >>= 1) {
            for (int i = tid; i < TT; i += 1024) {
                int ixj = i ^ j;
                if (ixj > i) {
                    bool up = ((i & k) == 0);
                    unsigned long long a = keys[i], c = keys[ixj];
                    if ((a > c) == up) { keys[i] = c; keys[ixj] = a; }
                }
            }
            __syncthreads();
        }
    int* sidx = (int*)&keys[KSEL];
    for (int i = tid; i < KSEL; i += 1024)
        sidx[i] = (int)(unsigned)(keys[i] & 0xFFFFFFFFull);
    __syncthreads();
    for (int k = 2; k <= KSEL; k <<= 1)
        for (int j = k >> 1; j > 0; j >>= 1) {
            for (int i = tid; i < KSEL; i += 1024) {
                int ixj = i ^ j;
                if (ixj > i) {
                    bool up = ((i & k) == 0);
                    int a = sidx[i], c = sidx[ixj];
                    if ((a > c) == up) { sidx[i] = c; sidx[ixj] = a; }
                }
            }
            __syncthreads();
        }
    for (int i = tid; i < KSEL; i += 1024) g_idx[b * KSEL + i] = sidx[i];
}

// ---------------- gather + LN1 ----------------
__global__ void __launch_bounds__(256) gather_ln1_kernel(const float* __restrict__ x,
                                                         const float* __restrict__ sc,
                                                         const float* __restrict__ bi) {
    __shared__ float red[18];
    int r = blockIdx.x;
    int b = r >> 11;
    int tok = g_idx[r];
    const float* src = x + ((size_t)b * TT + tok) * DD;
    int t = threadIdx.x;
    float v[4], s = 0.f, q = 0.f;
    #pragma unroll
    for (int j = 0; j < 4; j++) { v[j] = src[t + 256 * j]; s += v[j]; q += v[j] * v[j]; }
    #pragma unroll
    for (int o = 16; o > 0; o >>= 1) { s += __shfl_xor_sync(~0u, s, o); q += __shfl_xor_sync(~0u, q, o); }
    int w = t >> 5, lane = t & 31;
    if (lane == 0) { red[w] = s; red[w + 8] = q; }
    __syncthreads();
    if (t == 0) {
        float ss = 0, qq = 0;
        #pragma unroll
        for (int i = 0; i < 8; i++) { ss += red[i]; qq += red[i + 8]; }
        red[16] = ss; red[17] = qq;
    }
    __syncthreads();
    float mean = red[16] * (1.f / DD);
    float var  = red[17] * (1.f / DD) - mean * mean;
    float inv  = rsqrtf(var + EPS_LN);
    float* xs = g_xsel   + (size_t)r * DD;
    float* nm = g_normed + (size_t)r * DD;
    #pragma unroll
    for (int j = 0; j < 4; j++) {
        int c = t + 256 * j;
        xs[c] = v[j];
        nm[c] = to_tf32((v[j] - mean) * inv * sc[c] + bi[c]);
    }
}

// ---------------- LN2 ----------------
__global__ void __launch_bounds__(256) ln2_kernel(const float* __restrict__ sc,
                                                  const float* __restrict__ bi) {
    __shared__ float red[18];
    int r = blockIdx.x;
    const float* src = g_xsel + (size_t)r * DD;
    int t = threadIdx.x;
    float v[4], s = 0.f, q = 0.f;
    #pragma unroll
    for (int j = 0; j < 4; j++) { v[j] = src[t + 256 * j]; s += v[j]; q += v[j] * v[j]; }
    #pragma unroll
    for (int o = 16; o > 0; o >>= 1) { s += __shfl_xor_sync(~0u, s, o); q += __shfl_xor_sync(~0u, q, o); }
    int w = t >> 5, lane = t & 31;
    if (lane == 0) { red[w] = s; red[w + 8] = q; }
    __syncthreads();
    if (t == 0) {
        float ss = 0, qq = 0;
        #pragma unroll
        for (int i = 0; i < 8; i++) { ss += red[i]; qq += red[i + 8]; }
        red[16] = ss; red[17] = qq;
    }
    __syncthreads();
    float mean = red[16] * (1.f / DD);
    float var  = red[17] * (1.f / DD) - mean * mean;
    float inv  = rsqrtf(var + EPS_LN);
    float* nm = g_normed + (size_t)r * DD;
    #pragma unroll
    for (int j = 0; j < 4; j++) {
        int c = t + 256 * j;
        nm[c] = to_tf32((v[j] - mean) * inv * sc[c] + bi[c]);
    }
}

// ---------------- tf32 mma.sync GEMM: C[M,N] (+)= A[M,K] * B[N,K]^T ----------------
// 128x128 CTA tile, BK=32, 3-stage cp.async, 8 warps (4M x 2N), warp tile 32x64.
#define GSTAGES  3
#define TILE_B   16384                // 128 rows * 32 floats * 4B
#define STAGE_B  (2 * TILE_B)         // A + B
#define GEMM_SMEM (GSTAGES * STAGE_B)

// swizzled byte offset within a [128 rows x 128B] tile
__device__ __forceinline__ uint32_t swzoff(int r, int cByte) {
    return (uint32_t)(r * 128 + (cByte ^ ((r & 7) << 4)));
}

__device__ __forceinline__ void load_tile_pair(uint32_t sA, const float* Ag, const float* Bg,
                                               int K, int k0, int tid) {
    uint32_t sB = sA + TILE_B;
    #pragma unroll
    for (int j = 0; j < 4; j++) {
        int u = tid + 256 * j;
        int r = u >> 3, c16 = u & 7;
        cp16(sA + swzoff(r, c16 * 16), Ag + (size_t)r * K + k0 + c16 * 4);
    }
    #pragma unroll
    for (int j = 0; j < 4; j++) {
        int u = tid + 256 * j;
        int r = u >> 3, c16 = u & 7;
        cp16(sB + swzoff(r, c16 * 16), Bg + (size_t)r * K + k0 + c16 * 4);
    }
}

template<int ADD>
__global__ void __launch_bounds__(256) mma_gemm(const float* __restrict__ A,
                                                const float* __restrict__ Bw,
                                                float* __restrict__ C,
                                                int M, int N, int K) {
    extern __shared__ char sm[];
    const uint32_t sbase = smem_u32(sm);
    const int tid = threadIdx.x, wid = tid >> 5, lane = tid & 31;
    const int bn = blockIdx.x * 128, bm = blockIdx.y * 128;
    const int wm = wid >> 1, wn = wid & 1;

    const float* Ag = A  + (size_t)bm * K;
    const float* Bg = Bw + (size_t)bn * K;
    const int nch = K >> 5;

    float acc[2][8][4];
    #pragma unroll
    for (int mt = 0; mt < 2; mt++)
        #pragma unroll
        for (int nt = 0; nt < 8; nt++)
            #pragma unroll
            for (int e = 0; e < 4; e++) acc[mt][nt][e] = 0.f;

    // fragment row/col indices within the CTA tile
    const int arow = wm * 32 + (lane >> 2);   // + {0,8,16,24}
    const int acol = lane & 3;                // + {0,4} + k0
    const int brow = wn * 64 + (lane >> 2);   // + nt*8
    const int bcol = lane & 3;                // + {0,4} + k0

    // prologue
    load_tile_pair(sbase + 0 * STAGE_B, Ag, Bg, K, 0,  tid);
    cp_commit();
    load_tile_pair(sbase + 1 * STAGE_B, Ag, Bg, K, 32, tid);
    cp_commit();

    for (int i = 0; i < nch; i++) {
        if (i + 2 < nch)
            load_tile_pair(sbase + ((i + 2) % 3) * STAGE_B, Ag, Bg, K, (i + 2) * 32, tid);
        cp_commit();
        cp_wait2();
        __syncthreads();
        const uint32_t sA = sbase + (i % 3) * STAGE_B;
        const uint32_t sB = sA + TILE_B;
        #pragma unroll
        for (int ks = 0; ks < 4; ks++) {
            const int k0 = ks * 8;
            uint32_t a[2][4];
            #pragma unroll
            for (int mt = 0; mt < 2; mt++) {
                int r0 = arow + mt * 16, r1 = r0 + 8;
                asm volatile("ld.shared.b32 %0, [%1];" : "=r"(a[mt][0]) : "r"(sA + swzoff(r0, (k0 + acol) * 4)));
                asm volatile("ld.shared.b32 %0, [%1];" : "=r"(a[mt][1]) : "r"(sA + swzoff(r1, (k0 + acol) * 4)));
                asm volatile("ld.shared.b32 %0, [%1];" : "=r"(a[mt][2]) : "r"(sA + swzoff(r0, (k0 + acol + 4) * 4)));
                asm volatile("ld.shared.b32 %0, [%1];" : "=r"(a[mt][3]) : "r"(sA + swzoff(r1, (k0 + acol + 4) * 4)));
            }
            uint32_t b[8][2];
            #pragma unroll
            for (int nt = 0; nt < 8; nt++) {
                int rn = brow + nt * 8;
                asm volatile("ld.shared.b32 %0, [%1];" : "=r"(b[nt][0]) : "r"(sB + swzoff(rn, (k0 + bcol) * 4)));
                asm volatile("ld.shared.b32 %0, [%1];" : "=r"(b[nt][1]) : "r"(sB + swzoff(rn, (k0 + bcol + 4) * 4)));
            }
            #pragma unroll
            for (int mt = 0; mt < 2; mt++)
                #pragma unroll
                for (int nt = 0; nt < 8; nt++)
                    mma_tf32(acc[mt][nt], a[mt][0], a[mt][1], a[mt][2], a[mt][3],
                             b[nt][0], b[nt][1]);
        }
        __syncthreads();
    }

    // epilogue
    #pragma unroll
    for (int mt = 0; mt < 2; mt++) {
        #pragma unroll
        for (int nt = 0; nt < 8; nt++) {
            int row = bm + wm * 32 + mt * 16 + (lane >> 2);
            int col = bn + wn * 64 + nt * 8 + (lane & 3) * 2;
            float* C0 = C + (size_t)row * N + col;
            float* C1 = C + (size_t)(row + 8) * N + col;
            float2 v0 = make_float2(acc[mt][nt][0], acc[mt][nt][1]);
            float2 v1 = make_float2(acc[mt][nt][2], acc[mt][nt][3]);
            if (ADD) {
                float2 o0 = *(float2*)C0, o1 = *(float2*)C1;
                v0.x += o0.x; v0.y += o0.y; v1.x += o1.x; v1.y += o1.y;
            }
            *(float2*)C0 = v0;
            *(float2*)C1 = v1;
        }
    }
}

// ---------------- flash attention (fp32 SIMT; output tf32-rounded) ----------------
__global__ void __launch_bounds__(256) flash_kernel() {
    __shared__ float Qt[64][64];
    __shared__ float Kt[64][64];
    __shared__ float Vs[64][64];
    const int b = blockIdx.z, h = blockIdx.y, qt = blockIdx.x;
    const int tid = threadIdx.x, ty = tid >> 4, tx = tid & 15;
    const float* base = g_qkv + (size_t)b * KSEL * (3 * DD);
    {
        int r = tid >> 2, c0 = (tid & 3) * 4;
        const float* Qg = base + (size_t)(qt * 64) * (3 * DD) + h * HD;
        #pragma unroll
        for (int it = 0; it < 4; it++) {
            int c = it * 16 + c0;
            float4 v = *(const float4*)(Qg + (size_t)r * (3 * DD) + c);
            Qt[c][r] = v.x; Qt[c + 1][r] = v.y; Qt[c + 2][r] = v.z; Qt[c + 3][r] = v.w;
        }
    }
    float o[4][4], m_[4], l_[4];
    #pragma unroll
    for (int i = 0; i < 4; i++) {
        m_[i] = -1e30f; l_[i] = 0.f;
        #pragma unroll
        for (int j = 0; j < 4; j++) o[i][j] = 0.f;
    }
    for (int kt = 0; kt < KSEL / 64; kt++) {
        __syncthreads();
        {
            int r = tid >> 2, c0 = (tid & 3) * 4;
            const float* Kg = base + (size_t)(kt * 64) * (3 * DD) + DD + h * HD;
            const float* Vg = base + (size_t)(kt * 64) * (3 * DD) + 2 * DD + h * HD;
            #pragma unroll
            for (int it = 0; it < 4; it++) {
                int c = it * 16 + c0;
                float4 kv4 = *(const float4*)(Kg + (size_t)r * (3 * DD) + c);
                Kt[c][r] = kv4.x; Kt[c + 1][r] = kv4.y; Kt[c + 2][r] = kv4.z; Kt[c + 3][r] = kv4.w;
                float4 vv = *(const float4*)(Vg + (size_t)r * (3 * DD) + c);
                *(float4*)&Vs[r][c] = vv;
            }
        }
        __syncthreads();
        float s[4][4];
        #pragma unroll
        for (int i = 0; i < 4; i++)
            #pragma unroll
            for (int j = 0; j < 4; j++) s[i][j] = 0.f;
        #pragma unroll 8
        for (int d = 0; d < 64; d++) {
            float aq[4], bk[4];
            #pragma unroll
            for (int i = 0; i < 4; i++) aq[i] = Qt[d][ty * 4 + i];
            #pragma unroll
            for (int j = 0; j < 4; j++) bk[j] = Kt[d][tx * 4 + j];
            #pragma unroll
            for (int i = 0; i < 4; i++)
                #pragma unroll
                for (int j = 0; j < 4; j++)
                    s[i][j] += aq[i] * bk[j];
        }
        #pragma unroll
        for (int i = 0; i < 4; i++) {
            float tm = -1e30f;
            #pragma unroll
            for (int j = 0; j < 4; j++) { s[i][j] *= 0.125f; tm = fmaxf(tm, s[i][j]); }
            #pragma unroll
            for (int off = 1; off < 16; off <<= 1) tm = fmaxf(tm, __shfl_xor_sync(~0u, tm, off));
            float nm = fmaxf(m_[i], tm);
            float corr = __expf(m_[i] - nm);
            float rs = 0.f;
            #pragma unroll
            for (int j = 0; j < 4; j++) { s[i][j] = __expf(s[i][j] - nm); rs += s[i][j]; }
            #pragma unroll
            for (int off = 1; off < 16; off <<= 1) rs += __shfl_xor_sync(~0u, rs, off);
            l_[i] = l_[i] * corr + rs;
            #pragma unroll
            for (int j = 0; j < 4; j++) o[i][j] *= corr;
            m_[i] = nm;
        }
        __syncthreads();
        #pragma unroll
        for (int i = 0; i < 4; i++)
            #pragma unroll
            for (int j = 0; j < 4; j++)
                Kt[tx * 4 + j][ty * 4 + i] = s[i][j];
        __syncthreads();
        #pragma unroll 8
        for (int kv = 0; kv < 64; kv++) {
            float p[4], vv[4];
            #pragma unroll
            for (int i = 0; i < 4; i++) p[i] = Kt[kv][ty * 4 + i];
            #pragma unroll
            for (int j = 0; j < 4; j++) vv[j] = Vs[kv][tx * 4 + j];
            #pragma unroll
            for (int i = 0; i < 4; i++)
                #pragma unroll
                for (int j = 0; j < 4; j++)
                    o[i][j] += p[i] * vv[j];
        }
    }
    #pragma unroll
    for (int i = 0; i < 4; i++) {
        float inv = 1.f / l_[i];
        size_t row = (size_t)(b * KSEL + qt * 64 + ty * 4 + i);
        #pragma unroll
        for (int j = 0; j < 4; j++)
            g_o[row * DD + h * HD + tx * 4 + j] = to_tf32(o[i][j] * inv);
    }
}

// ---------------- SwiGLU (output tf32-rounded, feeds w3 GEMM) ----------------
__global__ void __launch_bounds__(256) swiglu_kernel() {
    size_t i = (size_t)blockIdx.x * blockDim.x + threadIdx.x;
    float4 a = ((const float4*)g_h1)[i];
    float4 c = ((const float4*)g_h2)[i];
    a.x = to_tf32(a.x / (1.f + __expf(-a.x)) * c.x);
    a.y = to_tf32(a.y / (1.f + __expf(-a.y)) * c.y);
    a.z = to_tf32(a.z / (1.f + __expf(-a.z)) * c.z);
    a.w = to_tf32(a.w / (1.f + __expf(-a.w)) * c.w);
    ((float4*)g_h1)[i] = a;
}

// ---------------- copy + scatter ----------------
__global__ void __launch_bounds__(256) copy_kernel(float* __restrict__ out,
                                                   const float* __restrict__ x) {
    size_t i = (size_t)blockIdx.x * blockDim.x + threadIdx.x;
    ((float4*)out)[i] = ((const float4*)x)[i];
}

__global__ void __launch_bounds__(256) scatter_kernel(float* __restrict__ out) {
    int r = blockIdx.x;
    int b = r >> 11;
    int tok = g_idx[r];
    float4 v = ((const float4*)(g_xsel + (size_t)r * DD))[threadIdx.x];
    ((float4*)(out + ((size_t)b * TT + tok) * DD))[threadIdx.x] = v;
}

// ---------------- launcher ----------------
extern "C" void kernel_launch(void* const* d_in, const int* in_sizes, int n_in,
                              void* d_out, int out_size) {
    const float* x        = (const float*)d_in[0];
    const float* w_router = (const float*)d_in[1];
    const float* ln1s     = (const float*)d_in[2];
    const float* ln1b     = (const float*)d_in[3];
    const float* ln2s     = (const float*)d_in[4];
    const float* ln2b     = (const float*)d_in[5];
    const float* w_qkv    = (const float*)d_in[6];
    const float* w_out    = (const float*)d_in[7];
    const float* w1       = (const float*)d_in[8];
    const float* w2       = (const float*)d_in[9];
    const float* w3       = (const float*)d_in[10];
    float* out = (float*)d_out;

    float *p_xsel, *p_normed, *p_qkv, *p_o, *p_h1, *p_h2;
    float *p_wqkv, *p_wout, *p_w1, *p_w2, *p_w3;
    cudaGetSymbolAddress((void**)&p_xsel,   g_xsel);
    cudaGetSymbolAddress((void**)&p_normed, g_normed);
    cudaGetSymbolAddress((void**)&p_qkv,    g_qkv);
    cudaGetSymbolAddress((void**)&p_o,      g_o);
    cudaGetSymbolAddress((void**)&p_h1,     g_h1);
    cudaGetSymbolAddress((void**)&p_h2,     g_h2);
    cudaGetSymbolAddress((void**)&p_wqkv,   g_wqkv_r);
    cudaGetSymbolAddress((void**)&p_wout,   g_wout_r);
    cudaGetSymbolAddress((void**)&p_w1,     g_w1_r);
    cudaGetSymbolAddress((void**)&p_w2,     g_w2_r);
    cudaGetSymbolAddress((void**)&p_w3,     g_w3_r);

    cudaFuncSetAttribute(mma_gemm<0>, cudaFuncAttributeMaxDynamicSharedMemorySize, GEMM_SMEM);
    cudaFuncSetAttribute(mma_gemm<1>, cudaFuncAttributeMaxDynamicSharedMemorySize, GEMM_SMEM);

    init_kernel<<<1, 32>>>();
    router_kernel<<<(BB * TT) / 8, 256>>>(x, w_router);
    if (out_size > BB * TT * DD)
        aux_kernel<<<1, 32>>>(out, (size_t)out_size - 1);
    topk_kernel<<<BB, 1024>>>();

    round_tf32_kernel<<<3 * DD * DD / 1024, 256>>>(p_wqkv, w_qkv);
    round_tf32_kernel<<<DD * DD / 1024, 256>>>(p_wout, w_out);
    round_tf32_kernel<<<DFF_ * DD / 1024, 256>>>(p_w1, w1);
    round_tf32_kernel<<<DFF_ * DD / 1024, 256>>>(p_w2, w2);
    round_tf32_kernel<<<DD * DFF_ / 1024, 256>>>(p_w3, w3);

    gather_ln1_kernel<<<MR, 256>>>(x, ln1s, ln1b);

    // QKV: (8192 x 3072) = normed @ w_qkv^T
    mma_gemm<0><<<dim3(3 * DD / 128, MR / 128), 256, GEMM_SMEM>>>(p_normed, p_wqkv, p_qkv, MR, 3 * DD, DD);
    flash_kernel<<<dim3(KSEL / 64, HH, BB), 256>>>();
    // x_sel += o @ w_out^T
    mma_gemm<1><<<dim3(DD / 128, MR / 128), 256, GEMM_SMEM>>>(p_o, p_wout, p_xsel, MR, DD, DD);
    ln2_kernel<<<MR, 256>>>(ln2s, ln2b);
    // FFN
    mma_gemm<0><<<dim3(DFF_ / 128, MR / 128), 256, GEMM_SMEM>>>(p_normed, p_w1, p_h1, MR, DFF_, DD);
    mma_gemm<0><<<dim3(DFF_ / 128, MR / 128), 256, GEMM_SMEM>>>(p_normed, p_w2, p_h2, MR, DFF_, DD);
    swiglu_kernel<<<((size_t)MR * DFF_ / 4) / 256, 256>>>();
    mma_gemm<1><<<dim3(DD / 128, MR / 128), 256, GEMM_SMEM>>>(p_h1, p_w3, p_xsel, MR, DD, DFF_);

    copy_kernel<<<((size_t)BB * TT * DD / 4) / 256, 256>>>(out, x);
    scatter_kernel<<<MR, 256>>>(out);
}

// round 4
// speedup vs baseline: 4.3257x; 1.2949x over previous
#include <cuda_runtime.h>
#include <cuda_bf16.h>
#include <math.h>
#include <stdint.h>

// ---------------- problem constants ----------------
#define BB   4
#define TT   4096
#define DD   1024
#define HH   16
#define HD   64
#define DFF_ 4096
#define KSEL 2048
#define MR   (BB * KSEL)
#define EPS_LN 1e-5f

// ---------------- device scratch ----------------
__device__ float  g_logit[BB * TT];
__device__ double g_bsum[BB];
__device__ int    g_idx[MR];
__device__ float  g_xsel[(size_t)MR * DD];
__device__ float  g_normed[(size_t)MR * DD];
__device__ float  g_qkv[(size_t)MR * 3 * DD];
__device__ float  g_o[(size_t)MR * DD];
__device__ float  g_h1[(size_t)MR * DFF_];
// tf32-rounded weight copies
__device__ float  g_wqkv_r[3 * DD * DD];
__device__ float  g_wout_r[DD * DD];
__device__ float  g_w1_r[(size_t)DFF_ * DD];
__device__ float  g_w2_r[(size_t)DFF_ * DD];
__device__ float  g_w3_r[(size_t)DD * DFF_];

// ---------------- helpers ----------------
__device__ __forceinline__ float to_tf32(float x) {
    uint32_t u;
    asm("cvt.rna.tf32.f32 %0, %1;" : "=r"(u) : "f"(x));
    return __uint_as_float(u);
}
__device__ __forceinline__ uint32_t smem_u32(const void* p) {
    uint32_t a;
    asm("{ .reg .u64 t; cvta.to.shared.u64 t, %1; cvt.u32.u64 %0, t; }" : "=r"(a) : "l"(p));
    return a;
}
__device__ __forceinline__ void cp16(uint32_t dst, const void* src) {
    asm volatile("cp.async.cg.shared.global [%0], [%1], 16;" :: "r"(dst), "l"(src));
}
__device__ __forceinline__ void cp_commit() { asm volatile("cp.async.commit_group;" ::: "memory"); }
__device__ __forceinline__ void cp_wait2()  { asm volatile("cp.async.wait_group 2;"  ::: "memory"); }
__device__ __forceinline__ void cp_wait1()  { asm volatile("cp.async.wait_group 1;"  ::: "memory"); }
__device__ __forceinline__ void cp_wait0()  { asm volatile("cp.async.wait_group 0;"  ::: "memory"); }

__device__ __forceinline__ void mma_tf32(float c[4],
                                         uint32_t a0, uint32_t a1, uint32_t a2, uint32_t a3,
                                         uint32_t b0, uint32_t b1) {
    asm volatile("mma.sync.aligned.m16n8k8.row.col.f32.tf32.tf32.f32 "
        "{%0,%1,%2,%3}, {%4,%5,%6,%7}, {%8,%9}, {%0,%1,%2,%3};"
        : "+f"(c[0]), "+f"(c[1]), "+f"(c[2]), "+f"(c[3])
        : "r"(a0), "r"(a1), "r"(a2), "r"(a3), "r"(b0), "r"(b1));
}

// ---------------- init ----------------
__global__ void init_kernel() {
    if (threadIdx.x < BB) g_bsum[threadIdx.x] = 0.0;
}

// ---------------- round weights to tf32 ----------------
__global__ void __launch_bounds__(256) round_tf32_kernel(float* __restrict__ dst,
                                                         const float* __restrict__ src) {
    size_t i = (size_t)blockIdx.x * 256 + threadIdx.x;
    float4 v = ((const float4*)src)[i];
    v.x = to_tf32(v.x); v.y = to_tf32(v.y); v.z = to_tf32(v.z); v.w = to_tf32(v.w);
    ((float4*)dst)[i] = v;
}

// ---------------- router ----------------
__global__ void __launch_bounds__(256) router_kernel(const float* __restrict__ x,
                                                     const float* __restrict__ w) {
    int warp = threadIdx.x >> 5, lane = threadIdx.x & 31;
    int row  = blockIdx.x * 8 + warp;
    const float* xr = x + (size_t)row * DD;
    double acc = 0.0;
    #pragma unroll 8
    for (int i = lane; i < DD; i += 32) acc += (double)xr[i] * (double)w[i];
    #pragma unroll
    for (int o = 16; o > 0; o >>= 1) acc += __shfl_down_sync(0xffffffffu, acc, o);
    if (lane == 0) {
        g_logit[row] = (float)acc;
        double sig = 1.0 / (1.0 + exp(-acc));
        atomicAdd(&g_bsum[row / TT], sig);
    }
}

__global__ void aux_kernel(float* out, size_t aux_idx) {
    if (threadIdx.x == 0) {
        double m[BB], mu = 0.0;
        for (int b = 0; b < BB; b++) { m[b] = g_bsum[b] / (double)TT; mu += m[b]; }
        mu /= (double)BB;
        double v = 0.0;
        for (int b = 0; b < BB; b++) { double d = m[b] - mu; v += d * d; }
        v /= (double)(BB - 1);
        out[aux_idx] = (float)v;
    }
}

// ---------------- top-k ----------------
__global__ void __launch_bounds__(1024) topk_kernel() {
    __shared__ unsigned long long keys[TT];
    int b = blockIdx.x, tid = threadIdx.x;
    for (int i = tid; i < TT; i += 1024) {
        unsigned u = __float_as_uint(g_logit[b * TT + i]);
        u = (u & 0x80000000u) ? ~u : (u | 0x80000000u);
        u = ~u;
        keys[i] = ((unsigned long long)u << 32) | (unsigned)i;
    }
    __syncthreads();
    for (int k = 2; k <= TT; k <<= 1)
        for (int j = k >> 1; j > 0; j >>= 1) {
            for (int i = tid; i < TT; i += 1024) {
                int ixj = i ^ j;
                if (ixj > i) {
                    bool up = ((i & k) == 0);
                    unsigned long long a = keys[i], c = keys[ixj];
                    if ((a > c) == up) { keys[i] = c; keys[ixj] = a; }
                }
            }
            __syncthreads();
        }
    int* sidx = (int*)&keys[KSEL];
    for (int i = tid; i < KSEL; i += 1024)
        sidx[i] = (int)(unsigned)(keys[i] & 0xFFFFFFFFull);
    __syncthreads();
    for (int k = 2; k <= KSEL; k <<= 1)
        for (int j = k >> 1; j > 0; j >>= 1) {
            for (int i = tid; i < KSEL; i += 1024) {
                int ixj = i ^ j;
                if (ixj > i) {
                    bool up = ((i & k) == 0);
                    int a = sidx[i], c = sidx[ixj];
                    if ((a > c) == up) { sidx[i] = c; sidx[ixj] = a; }
                }
            }
            __syncthreads();
        }
    for (int i = tid; i < KSEL; i += 1024) g_idx[b * KSEL + i] = sidx[i];
}

// ---------------- gather + LN1 ----------------
__global__ void __launch_bounds__(256) gather_ln1_kernel(const float* __restrict__ x,
                                                         const float* __restrict__ sc,
                                                         const float* __restrict__ bi) {
    __shared__ float red[18];
    int r = blockIdx.x;
    int b = r >> 11;
    int tok = g_idx[r];
    const float* src = x + ((size_t)b * TT + tok) * DD;
    int t = threadIdx.x;
    float v[4], s = 0.f, q = 0.f;
    #pragma unroll
    for (int j = 0; j < 4; j++) { v[j] = src[t + 256 * j]; s += v[j]; q += v[j] * v[j]; }
    #pragma unroll
    for (int o = 16; o > 0; o >>= 1) { s += __shfl_xor_sync(~0u, s, o); q += __shfl_xor_sync(~0u, q, o); }
    int w = t >> 5, lane = t & 31;
    if (lane == 0) { red[w] = s; red[w + 8] = q; }
    __syncthreads();
    if (t == 0) {
        float ss = 0, qq = 0;
        #pragma unroll
        for (int i = 0; i < 8; i++) { ss += red[i]; qq += red[i + 8]; }
        red[16] = ss; red[17] = qq;
    }
    __syncthreads();
    float mean = red[16] * (1.f / DD);
    float var  = red[17] * (1.f / DD) - mean * mean;
    float inv  = rsqrtf(var + EPS_LN);
    float* xs = g_xsel   + (size_t)r * DD;
    float* nm = g_normed + (size_t)r * DD;
    #pragma unroll
    for (int j = 0; j < 4; j++) {
        int c = t + 256 * j;
        xs[c] = v[j];
        nm[c] = to_tf32((v[j] - mean) * inv * sc[c] + bi[c]);
    }
}

// ---------------- LN2 ----------------
__global__ void __launch_bounds__(256) ln2_kernel(const float* __restrict__ sc,
                                                  const float* __restrict__ bi) {
    __shared__ float red[18];
    int r = blockIdx.x;
    const float* src = g_xsel + (size_t)r * DD;
    int t = threadIdx.x;
    float v[4], s = 0.f, q = 0.f;
    #pragma unroll
    for (int j = 0; j < 4; j++) { v[j] = src[t + 256 * j]; s += v[j]; q += v[j] * v[j]; }
    #pragma unroll
    for (int o = 16; o > 0; o >>= 1) { s += __shfl_xor_sync(~0u, s, o); q += __shfl_xor_sync(~0u, q, o); }
    int w = t >> 5, lane = t & 31;
    if (lane == 0) { red[w] = s; red[w + 8] = q; }
    __syncthreads();
    if (t == 0) {
        float ss = 0, qq = 0;
        #pragma unroll
        for (int i = 0; i < 8; i++) { ss += red[i]; qq += red[i + 8]; }
        red[16] = ss; red[17] = qq;
    }
    __syncthreads();
    float mean = red[16] * (1.f / DD);
    float var  = red[17] * (1.f / DD) - mean * mean;
    float inv  = rsqrtf(var + EPS_LN);
    float* nm = g_normed + (size_t)r * DD;
    #pragma unroll
    for (int j = 0; j < 4; j++) {
        int c = t + 256 * j;
        nm[c] = to_tf32((v[j] - mean) * inv * sc[c] + bi[c]);
    }
}

// ---------------- tf32 mma.sync GEMM: C[M,N] (+)= A[M,K] * B[N,K]^T ----------------
// EP: 0 = store, 1 = add+store, 2 = tf32-round+store, 3 = swiglu: C = tf32(silu(C)*acc)
#define GSTAGES  3
#define TILE_B   16384
#define STAGE_B  (2 * TILE_B)
#define GEMM_SMEM (GSTAGES * STAGE_B)

__device__ __forceinline__ uint32_t swzoff(int r, int cByte) {
    return (uint32_t)(r * 128 + (cByte ^ ((r & 7) << 4)));
}

__device__ __forceinline__ void load_tile_pair(uint32_t sA, const float* Ag, const float* Bg,
                                               int K, int k0, int tid) {
    uint32_t sB = sA + TILE_B;
    #pragma unroll
    for (int j = 0; j < 4; j++) {
        int u = tid + 256 * j;
        int r = u >> 3, c16 = u & 7;
        cp16(sA + swzoff(r, c16 * 16), Ag + (size_t)r * K + k0 + c16 * 4);
    }
    #pragma unroll
    for (int j = 0; j < 4; j++) {
        int u = tid + 256 * j;
        int r = u >> 3, c16 = u & 7;
        cp16(sB + swzoff(r, c16 * 16), Bg + (size_t)r * K + k0 + c16 * 4);
    }
}

template<int EP>
__global__ void __launch_bounds__(256) mma_gemm(const float* __restrict__ A,
                                                const float* __restrict__ Bw,
                                                float* __restrict__ C,
                                                int M, int N, int K) {
    extern __shared__ char sm[];
    const uint32_t sbase = smem_u32(sm);
    const int tid = threadIdx.x, wid = tid >> 5, lane = tid & 31;
    const int bn = blockIdx.x * 128, bm = blockIdx.y * 128;
    const int wm = wid >> 1, wn = wid & 1;

    const float* Ag = A  + (size_t)bm * K;
    const float* Bg = Bw + (size_t)bn * K;
    const int nch = K >> 5;

    float acc[2][8][4];
    #pragma unroll
    for (int mt = 0; mt < 2; mt++)
        #pragma unroll
        for (int nt = 0; nt < 8; nt++)
            #pragma unroll
            for (int e = 0; e < 4; e++) acc[mt][nt][e] = 0.f;

    const int arow = wm * 32 + (lane >> 2);
    const int acol = lane & 3;
    const int brow = wn * 64 + (lane >> 2);
    const int bcol = lane & 3;

    load_tile_pair(sbase + 0 * STAGE_B, Ag, Bg, K, 0,  tid);
    cp_commit();
    load_tile_pair(sbase + 1 * STAGE_B, Ag, Bg, K, 32, tid);
    cp_commit();

    for (int i = 0; i < nch; i++) {
        if (i + 2 < nch)
            load_tile_pair(sbase + ((i + 2) % 3) * STAGE_B, Ag, Bg, K, (i + 2) * 32, tid);
        cp_commit();
        cp_wait2();
        __syncthreads();
        const uint32_t sA = sbase + (i % 3) * STAGE_B;
        const uint32_t sB = sA + TILE_B;
        #pragma unroll
        for (int ks = 0; ks < 4; ks++) {
            const int k0 = ks * 8;
            uint32_t a[2][4];
            #pragma unroll
            for (int mt = 0; mt < 2; mt++) {
                int r0 = arow + mt * 16, r1 = r0 + 8;
                asm volatile("ld.shared.b32 %0, [%1];" : "=r"(a[mt][0]) : "r"(sA + swzoff(r0, (k0 + acol) * 4)));
                asm volatile("ld.shared.b32 %0, [%1];" : "=r"(a[mt][1]) : "r"(sA + swzoff(r1, (k0 + acol) * 4)));
                asm volatile("ld.shared.b32 %0, [%1];" : "=r"(a[mt][2]) : "r"(sA + swzoff(r0, (k0 + acol + 4) * 4)));
                asm volatile("ld.shared.b32 %0, [%1];" : "=r"(a[mt][3]) : "r"(sA + swzoff(r1, (k0 + acol + 4) * 4)));
            }
            uint32_t b[8][2];
            #pragma unroll
            for (int nt = 0; nt < 8; nt++) {
                int rn = brow + nt * 8;
                asm volatile("ld.shared.b32 %0, [%1];" : "=r"(b[nt][0]) : "r"(sB + swzoff(rn, (k0 + bcol) * 4)));
                asm volatile("ld.shared.b32 %0, [%1];" : "=r"(b[nt][1]) : "r"(sB + swzoff(rn, (k0 + bcol + 4) * 4)));
            }
            #pragma unroll
            for (int mt = 0; mt < 2; mt++)
                #pragma unroll
                for (int nt = 0; nt < 8; nt++)
                    mma_tf32(acc[mt][nt], a[mt][0], a[mt][1], a[mt][2], a[mt][3],
                             b[nt][0], b[nt][1]);
        }
        __syncthreads();
    }

    #pragma unroll
    for (int mt = 0; mt < 2; mt++) {
        #pragma unroll
        for (int nt = 0; nt < 8; nt++) {
            int row = bm + wm * 32 + mt * 16 + (lane >> 2);
            int col = bn + wn * 64 + nt * 8 + (lane & 3) * 2;
            float* C0 = C + (size_t)row * N + col;
            float* C1 = C + (size_t)(row + 8) * N + col;
            float2 v0 = make_float2(acc[mt][nt][0], acc[mt][nt][1]);
            float2 v1 = make_float2(acc[mt][nt][2], acc[mt][nt][3]);
            if (EP == 1) {
                float2 o0 = *(float2*)C0, o1 = *(float2*)C1;
                v0.x += o0.x; v0.y += o0.y; v1.x += o1.x; v1.y += o1.y;
            } else if (EP == 2) {
                v0.x = to_tf32(v0.x); v0.y = to_tf32(v0.y);
                v1.x = to_tf32(v1.x); v1.y = to_tf32(v1.y);
            } else if (EP == 3) {
                float2 h0 = *(float2*)C0, h1v = *(float2*)C1;
                v0.x = to_tf32(h0.x  / (1.f + __expf(-h0.x))  * v0.x);
                v0.y = to_tf32(h0.y  / (1.f + __expf(-h0.y))  * v0.y);
                v1.x = to_tf32(h1v.x / (1.f + __expf(-h1v.x)) * v1.x);
                v1.y = to_tf32(h1v.y / (1.f + __expf(-h1v.y)) * v1.y);
            }
            *(float2*)C0 = v0;
            *(float2*)C1 = v1;
        }
    }
}

// ---------------- tensor-core flash attention ----------------
// CTA: 128 q-rows, 8 warps (16 rows each), K-tile = 64, tf32 mma.sync.
#define FPAD 68
#define PS_FLOATS   (128 * FPAD)
#define KV_FLOATS   (64 * FPAD)
#define FLASH_SMEM  ((PS_FLOATS + 4 * KV_FLOATS) * 4)

__global__ void __launch_bounds__(256) flash_tc_kernel() {
    extern __shared__ float fs[];
    const int b = blockIdx.z, h = blockIdx.y, qt = blockIdx.x;
    const int tid = threadIdx.x, wid = tid >> 5, lane = tid & 31;
    const int qr = lane >> 2, qc = lane & 3;
    const int wrow = wid * 16;
    const float* base = g_qkv + (size_t)b * KSEL * (3 * DD);
    const float* Qg = base + (size_t)(qt * 128) * (3 * DD) + h * HD;
    const float* Kg = base + DD + h * HD;
    const float* Vg = base + 2 * DD + h * HD;

    float* Ps = fs;                       // 128 x FPAD (also Q staging)
    float* Ks0 = fs + PS_FLOATS;
    float* Ks1 = Ks0 + KV_FLOATS;
    float* Vt0 = Ks1 + KV_FLOATS;
    float* Vt1 = Vt0 + KV_FLOATS;
    const uint32_t sKs0 = smem_u32(Ks0), sKs1 = smem_u32(Ks1);

    // ---- stage Q tile (scaled by 1/8) and read fragments ----
    for (int u = tid; u < 128 * 16; u += 256) {
        int r = u >> 4, c = (u & 15) * 4;
        float4 v = *(const float4*)(Qg + (size_t)r * (3 * DD) + c);
        v.x *= 0.125f; v.y *= 0.125f; v.z *= 0.125f; v.w *= 0.125f;
        *(float4*)(Ps + r * FPAD + c) = v;
    }
    __syncthreads();
    float qf[8][4];
    #pragma unroll
    for (int ks = 0; ks < 8; ks++) {
        qf[ks][0] = Ps[(wrow + qr)     * FPAD + ks * 8 + qc];
        qf[ks][1] = Ps[(wrow + qr + 8) * FPAD + ks * 8 + qc];
        qf[ks][2] = Ps[(wrow + qr)     * FPAD + ks * 8 + qc + 4];
        qf[ks][3] = Ps[(wrow + qr + 8) * FPAD + ks * 8 + qc + 4];
    }
    __syncthreads();      // Ps now free for P

    float o[8][4];
    #pragma unroll
    for (int nt = 0; nt < 8; nt++)
        #pragma unroll
        for (int e = 0; e < 4; e++) o[nt][e] = 0.f;
    float m_[2] = {-1e30f, -1e30f}, l_[2] = {0.f, 0.f};

    const int vkv = tid & 63, vdg = tid >> 6;
    float4 vreg[4];

    // prefetch tile 0
    for (int u = tid; u < 64 * 16; u += 256) {
        int r = u >> 4, c16 = u & 15;
        cp16(sKs0 + (r * FPAD + c16 * 4) * 4, Kg + (size_t)r * (3 * DD) + c16 * 4);
    }
    cp_commit();
    #pragma unroll
    for (int i = 0; i < 4; i++)
        vreg[i] = *(const float4*)(Vg + (size_t)vkv * (3 * DD) + (vdg + 4 * i) * 4);

    const int NTI = KSEL / 64;     // 32
    for (int t = 0; t < NTI; t++) {
        float* Ksb = (t & 1) ? Ks1 : Ks0;
        float* Vtb = (t & 1) ? Vt1 : Vt0;
        __syncthreads();           // all warps done with previous tile compute
        // store V[t] transposed
        #pragma unroll
        for (int i = 0; i < 4; i++) {
            int d0 = (vdg + 4 * i) * 4;
            Vtb[(d0 + 0) * FPAD + vkv] = vreg[i].x;
            Vtb[(d0 + 1) * FPAD + vkv] = vreg[i].y;
            Vtb[(d0 + 2) * FPAD + vkv] = vreg[i].z;
            Vtb[(d0 + 3) * FPAD + vkv] = vreg[i].w;
        }
        if (t + 1 < NTI) {
            uint32_t sKn = (t & 1) ? sKs0 : sKs1;
            const float* Kn = Kg + (size_t)((t + 1) * 64) * (3 * DD);
            for (int u = tid; u < 64 * 16; u += 256) {
                int r = u >> 4, c16 = u & 15;
                cp16(sKn + (r * FPAD + c16 * 4) * 4, Kn + (size_t)r * (3 * DD) + c16 * 4);
            }
            cp_commit();
            const float* Vn = Vg + (size_t)((t + 1) * 64) * (3 * DD);
            #pragma unroll
            for (int i = 0; i < 4; i++)
                vreg[i] = *(const float4*)(Vn + (size_t)vkv * (3 * DD) + (vdg + 4 * i) * 4);
            cp_wait1();
        } else {
            cp_wait0();
        }
        __syncthreads();           // K[t], V[t] visible

        // ---- S = Q K^T ----
        float s[8][4];
        #pragma unroll
        for (int nt = 0; nt < 8; nt++)
            #pragma unroll
            for (int e = 0; e < 4; e++) s[nt][e] = 0.f;
        #pragma unroll
        for (int ks = 0; ks < 8; ks++) {
            uint32_t bf[8][2];
            #pragma unroll
            for (int nt = 0; nt < 8; nt++) {
                bf[nt][0] = __float_as_uint(Ksb[(nt * 8 + qr) * FPAD + ks * 8 + qc]);
                bf[nt][1] = __float_as_uint(Ksb[(nt * 8 + qr) * FPAD + ks * 8 + qc + 4]);
            }
            #pragma unroll
            for (int nt = 0; nt < 8; nt++)
                mma_tf32(s[nt], __float_as_uint(qf[ks][0]), __float_as_uint(qf[ks][1]),
                                __float_as_uint(qf[ks][2]), __float_as_uint(qf[ks][3]),
                         bf[nt][0], bf[nt][1]);
        }
        // ---- online softmax ----
        float mx0 = -1e30f, mx1 = -1e30f;
        #pragma unroll
        for (int nt = 0; nt < 8; nt++) {
            mx0 = fmaxf(mx0, fmaxf(s[nt][0], s[nt][1]));
            mx1 = fmaxf(mx1, fmaxf(s[nt][2], s[nt][3]));
        }
        #pragma unroll
        for (int off = 1; off <= 2; off <<= 1) {
            mx0 = fmaxf(mx0, __shfl_xor_sync(~0u, mx0, off));
            mx1 = fmaxf(mx1, __shfl_xor_sync(~0u, mx1, off));
        }
        float nm0 = fmaxf(m_[0], mx0), nm1 = fmaxf(m_[1], mx1);
        float cr0 = __expf(m_[0] - nm0), cr1 = __expf(m_[1] - nm1);
        m_[0] = nm0; m_[1] = nm1;
        float rs0 = 0.f, rs1 = 0.f;
        #pragma unroll
        for (int nt = 0; nt < 8; nt++) {
            s[nt][0] = __expf(s[nt][0] - nm0); s[nt][1] = __expf(s[nt][1] - nm0);
            s[nt][2] = __expf(s[nt][2] - nm1); s[nt][3] = __expf(s[nt][3] - nm1);
            rs0 += s[nt][0] + s[nt][1];
            rs1 += s[nt][2] + s[nt][3];
        }
        #pragma unroll
        for (int off = 1; off <= 2; off <<= 1) {
            rs0 += __shfl_xor_sync(~0u, rs0, off);
            rs1 += __shfl_xor_sync(~0u, rs1, off);
        }
        l_[0] = l_[0] * cr0 + rs0;
        l_[1] = l_[1] * cr1 + rs1;
        #pragma unroll
        for (int nt = 0; nt < 8; nt++) {
            o[nt][0] *= cr0; o[nt][1] *= cr0;
            o[nt][2] *= cr1; o[nt][3] *= cr1;
        }
        // ---- write P (own rows only) ----
        #pragma unroll
        for (int nt = 0; nt < 8; nt++) {
            int c = nt * 8 + 2 * qc;
            *(float2*)(Ps + (wrow + qr)     * FPAD + c) = make_float2(s[nt][0], s[nt][1]);
            *(float2*)(Ps + (wrow + qr + 8) * FPAD + c) = make_float2(s[nt][2], s[nt][3]);
        }
        __syncwarp();
        // ---- O += P V ----
        #pragma unroll
        for (int ks = 0; ks < 8; ks++) {
            uint32_t a0 = __float_as_uint(Ps[(wrow + qr)     * FPAD + ks * 8 + qc]);
            uint32_t a1 = __float_as_uint(Ps[(wrow + qr + 8) * FPAD + ks * 8 + qc]);
            uint32_t a2 = __float_as_uint(Ps[(wrow + qr)     * FPAD + ks * 8 + qc + 4]);
            uint32_t a3 = __float_as_uint(Ps[(wrow + qr + 8) * FPAD + ks * 8 + qc + 4]);
            #pragma unroll
            for (int nt = 0; nt < 8; nt++) {
                uint32_t b0 = __float_as_uint(Vtb[(nt * 8 + qr) * FPAD + ks * 8 + qc]);
                uint32_t b1 = __float_as_uint(Vtb[(nt * 8 + qr) * FPAD + ks * 8 + qc + 4]);
                mma_tf32(o[nt], a0, a1, a2, a3, b0, b1);
            }
        }
        __syncwarp();
    }

    // ---- epilogue ----
    float inv0 = 1.f / l_[0], inv1 = 1.f / l_[1];
    size_t row0 = (size_t)(b * KSEL + qt * 128 + wrow + qr);
    size_t row1 = row0 + 8;
    #pragma unroll
    for (int nt = 0; nt < 8; nt++) {
        int col = h * HD + nt * 8 + 2 * qc;
        *(float2*)(g_o + row0 * DD + col) =
            make_float2(to_tf32(o[nt][0] * inv0), to_tf32(o[nt][1] * inv0));
        *(float2*)(g_o + row1 * DD + col) =
            make_float2(to_tf32(o[nt][2] * inv1), to_tf32(o[nt][3] * inv1));
    }
}

// ---------------- copy + scatter ----------------
__global__ void __launch_bounds__(256) copy_kernel(float* __restrict__ out,
                                                   const float* __restrict__ x) {
    size_t i = (size_t)blockIdx.x * blockDim.x + threadIdx.x;
    ((float4*)out)[i] = ((const float4*)x)[i];
}

__global__ void __launch_bounds__(256) scatter_kernel(float* __restrict__ out) {
    int r = blockIdx.x;
    int b = r >> 11;
    int tok = g_idx[r];
    float4 v = ((const float4*)(g_xsel + (size_t)r * DD))[threadIdx.x];
    ((float4*)(out + ((size_t)b * TT + tok) * DD))[threadIdx.x] = v;
}

// ---------------- launcher ----------------
extern "C" void kernel_launch(void* const* d_in, const int* in_sizes, int n_in,
                              void* d_out, int out_size) {
    const float* x        = (const float*)d_in[0];
    const float* w_router = (const float*)d_in[1];
    const float* ln1s     = (const float*)d_in[2];
    const float* ln1b     = (const float*)d_in[3];
    const float* ln2s     = (const float*)d_in[4];
    const float* ln2b     = (const float*)d_in[5];
    const float* w_qkv    = (const float*)d_in[6];
    const float* w_out    = (const float*)d_in[7];
    const float* w1       = (const float*)d_in[8];
    const float* w2       = (const float*)d_in[9];
    const float* w3       = (const float*)d_in[10];
    float* out = (float*)d_out;

    float *p_xsel, *p_normed, *p_qkv, *p_o, *p_h1;
    float *p_wqkv, *p_wout, *p_w1, *p_w2, *p_w3;
    cudaGetSymbolAddress((void**)&p_xsel,   g_xsel);
    cudaGetSymbolAddress((void**)&p_normed, g_normed);
    cudaGetSymbolAddress((void**)&p_qkv,    g_qkv);
    cudaGetSymbolAddress((void**)&p_o,      g_o);
    cudaGetSymbolAddress((void**)&p_h1,     g_h1);
    cudaGetSymbolAddress((void**)&p_wqkv,   g_wqkv_r);
    cudaGetSymbolAddress((void**)&p_wout,   g_wout_r);
    cudaGetSymbolAddress((void**)&p_w1,     g_w1_r);
    cudaGetSymbolAddress((void**)&p_w2,     g_w2_r);
    cudaGetSymbolAddress((void**)&p_w3,     g_w3_r);

    cudaFuncSetAttribute(mma_gemm<0>, cudaFuncAttributeMaxDynamicSharedMemorySize, GEMM_SMEM);
    cudaFuncSetAttribute(mma_gemm<1>, cudaFuncAttributeMaxDynamicSharedMemorySize, GEMM_SMEM);
    cudaFuncSetAttribute(mma_gemm<2>, cudaFuncAttributeMaxDynamicSharedMemorySize, GEMM_SMEM);
    cudaFuncSetAttribute(mma_gemm<3>, cudaFuncAttributeMaxDynamicSharedMemorySize, GEMM_SMEM);
    cudaFuncSetAttribute(flash_tc_kernel, cudaFuncAttributeMaxDynamicSharedMemorySize, FLASH_SMEM);

    init_kernel<<<1, 32>>>();
    router_kernel<<<(BB * TT) / 8, 256>>>(x, w_router);
    if (out_size > BB * TT * DD)
        aux_kernel<<<1, 32>>>(out, (size_t)out_size - 1);
    topk_kernel<<<BB, 1024>>>();

    round_tf32_kernel<<<3 * DD * DD / 1024, 256>>>(p_wqkv, w_qkv);
    round_tf32_kernel<<<DD * DD / 1024, 256>>>(p_wout, w_out);
    round_tf32_kernel<<<DFF_ * DD / 1024, 256>>>(p_w1, w1);
    round_tf32_kernel<<<DFF_ * DD / 1024, 256>>>(p_w2, w2);
    round_tf32_kernel<<<DD * DFF_ / 1024, 256>>>(p_w3, w3);

    gather_ln1_kernel<<<MR, 256>>>(x, ln1s, ln1b);

    // QKV (rounded epilogue so flash sees exact tf32 values)
    mma_gemm<2><<<dim3(3 * DD / 128, MR / 128), 256, GEMM_SMEM>>>(p_normed, p_wqkv, p_qkv, MR, 3 * DD, DD);
    // tensor-core flash attention
    flash_tc_kernel<<<dim3(KSEL / 128, HH, BB), 256, FLASH_SMEM>>>();
    // x_sel += o @ w_out^T
    mma_gemm<1><<<dim3(DD / 128, MR / 128), 256, GEMM_SMEM>>>(p_o, p_wout, p_xsel, MR, DD, DD);
    ln2_kernel<<<MR, 256>>>(ln2s, ln2b);
    // FFN: h1 = x@w1; h1 = tf32(silu(h1) * (x@w2)); xsel += h1 @ w3^T
    mma_gemm<0><<<dim3(DFF_ / 128, MR / 128), 256, GEMM_SMEM>>>(p_normed, p_w1, p_h1, MR, DFF_, DD);
    mma_gemm<3><<<dim3(DFF_ / 128, MR / 128), 256, GEMM_SMEM>>>(p_normed, p_w2, p_h1, MR, DFF_, DD);
    mma_gemm<1><<<dim3(DD / 128, MR / 128), 256, GEMM_SMEM>>>(p_h1, p_w3, p_xsel, MR, DD, DFF_);

    copy_kernel<<<((size_t)BB * TT * DD / 4) / 256, 256>>>(out, x);
    scatter_kernel<<<MR, 256>>>(out);
}